// round 2
// baseline (speedup 1.0000x reference)
#include <cuda_runtime.h>
#include <cuda_bf16.h>
#include <cstdint>

// Problem constants
#define Mv 8192
#define Nv 8192
#define Cv 80

// Scratch (no allocation allowed in kernel_launch)
__device__ float g_base[Nv];
__device__ int   g_perm[Mv];
__device__ int   g_off[Cv + 1];

__device__ __forceinline__ float softplus_stable(float x) {
    // log(1 + exp(x)) = max(x,0) + log1p(exp(-|x|))
    return fmaxf(x, 0.0f) + log1pf(expf(-fabsf(x)));
}

// Kernel 1: base[n] = sum_c softplus(pre_cls[n, c])
__global__ void base_kernel(const float* __restrict__ pc) {
    int n = blockIdx.x * blockDim.x + threadIdx.x;
    if (n >= Nv) return;
    const float4* row = reinterpret_cast<const float4*>(pc + (size_t)n * Cv);
    float s = 0.0f;
#pragma unroll
    for (int i = 0; i < Cv / 4; i++) {
        float4 v = row[i];
        s += softplus_stable(v.x) + softplus_stable(v.y) +
             softplus_stable(v.z) + softplus_stable(v.w);
    }
    g_base[n] = s;
}

// Kernel 2: counting sort of rows m by class g[m] -> g_perm, g_off
__global__ void group_kernel(const int* __restrict__ g) {
    __shared__ int cnt[Cv];
    __shared__ int offs[Cv + 1];
    int tid = threadIdx.x;
    if (tid < Cv) cnt[tid] = 0;
    __syncthreads();
    for (int m = tid; m < Mv; m += blockDim.x)
        atomicAdd(&cnt[g[m]], 1);
    __syncthreads();
    if (tid == 0) {
        int acc = 0;
        for (int c = 0; c < Cv; c++) { offs[c] = acc; acc += cnt[c]; }
        offs[Cv] = acc;
    }
    __syncthreads();
    if (tid <= Cv) g_off[tid] = offs[tid];
    if (tid < Cv)  cnt[tid] = offs[tid];   // reuse as cursor
    __syncthreads();
    for (int m = tid; m < Mv; m += blockDim.x) {
        int pos = atomicAdd(&cnt[g[m]], 1);
        g_perm[pos] = m;
    }
}

// Kernel 3: for class c and n-segment, compute the (base[n] - pre_cls[n,c])
// float4 once into registers, then stream it to every output row of class c.
// grid = (Nv / (256*4), Cv), block = 256
__global__ void __launch_bounds__(256) write_kernel(const float* __restrict__ pc,
                                                    float* __restrict__ out) {
    const int c  = blockIdx.y;
    const int n0 = (blockIdx.x * 256 + threadIdx.x) * 4;

    float4 b = *reinterpret_cast<const float4*>(g_base + n0);
    float4 v;
    v.x = b.x - pc[(size_t)(n0 + 0) * Cv + c];
    v.y = b.y - pc[(size_t)(n0 + 1) * Cv + c];
    v.z = b.z - pc[(size_t)(n0 + 2) * Cv + c];
    v.w = b.w - pc[(size_t)(n0 + 3) * Cv + c];

    const int i0 = g_off[c];
    const int i1 = g_off[c + 1];
    float4* out4 = reinterpret_cast<float4*>(out);
    const size_t col = (size_t)(n0 >> 2);

    for (int i = i0; i < i1; i++) {
        int m = g_perm[i];                      // broadcast load (same addr across warp)
        out4[(size_t)m * (Nv / 4) + col] = v;   // STG.128, coalesced across the block
    }
}

extern "C" void kernel_launch(void* const* d_in, const int* in_sizes, int n_in,
                              void* d_out, int out_size) {
    // Disambiguate input order by element counts (8192 vs 655360)
    const int*   g;
    const float* pc;
    if (in_sizes[0] == Mv) {
        g  = (const int*)d_in[0];
        pc = (const float*)d_in[1];
    } else {
        g  = (const int*)d_in[1];
        pc = (const float*)d_in[0];
    }
    float* out = (float*)d_out;

    base_kernel<<<(Nv + 255) / 256, 256>>>(pc);
    group_kernel<<<1, 1024>>>(g);
    dim3 grid(Nv / (256 * 4), Cv);
    write_kernel<<<grid, 256>>>(pc, out);
}